// round 15
// baseline (speedup 1.0000x reference)
#include <cuda_runtime.h>
#include <cuda_fp16.h>
#include <stdint.h>
#include <math.h>

#define B_TOTAL 4096
#define IN_F    1024
#define OUT_F   1024
#define NPER    9
#define KDIM    (IN_F * NPER)        // 9216

#define BM 256
#define BN 128
#define BKT 64
#define TILE_ITERS (KDIM / BKT)       // 144
#define MT_TILES (B_TOTAL / BM)       // 16
#define NT_TILES (OUT_F / BN)         // 8
#define TILES (MT_TILES * NT_TILES)   // 128
#define TOTAL_ITERS (TILES * TILE_ITERS)  // 18432
#define NWORKERS 148

#define NTHREADS 512
#define STAGES 4
#define A_BYTES (BM * BKT * 2)        // 32768
#define B_BYTES (BN * BKT * 2)        // 16384
#define STAGE_BYTES (A_BYTES + B_BYTES)      // 49152
#define SMEM_BYTES  (STAGES * STAGE_BYTES)   // 196608

#define PREP_BLOCKS 12288
#define PREP_GROUPS (NWORKERS * 2)    // 296 virtual 256-thread groups
#define PREP_STEPS  ((PREP_BLOCKS + PREP_GROUPS - 1) / PREP_GROUPS)  // 42

// fp16 matrices, row-major [rows][KDIM]
__device__ __half g_A[(size_t)B_TOTAL * KDIM];
__device__ __half g_B[(size_t)OUT_F * KDIM];

// global barrier state (sense-reversing; replay-safe)
__device__ unsigned g_count = 0;
__device__ unsigned g_sense = 0;

// ---------------------------------------------------------------------------
// PTX helpers (sm_80-legal)
// ---------------------------------------------------------------------------
__device__ __forceinline__ uint32_t smem_u32(const void* p) {
    return (uint32_t)__cvta_generic_to_shared(p);
}
__device__ __forceinline__ void cp16(uint32_t dst, const void* src) {
    asm volatile("cp.async.cg.shared.global [%0], [%1], 16;" :: "r"(dst), "l"(src) : "memory");
}
__device__ __forceinline__ void ldsm_x4(uint32_t* r, uint32_t addr) {
    asm volatile("ldmatrix.sync.aligned.m8n8.x4.shared.b16 {%0,%1,%2,%3}, [%4];"
                 : "=r"(r[0]), "=r"(r[1]), "=r"(r[2]), "=r"(r[3]) : "r"(addr));
}
__device__ __forceinline__ void mma_f16(float* d, const uint32_t* a, const uint32_t* b) {
    asm volatile(
        "mma.sync.aligned.m16n8k16.row.col.f32.f16.f16.f32 "
        "{%0,%1,%2,%3}, {%4,%5,%6,%7}, {%8,%9}, {%0,%1,%2,%3};"
        : "+f"(d[0]), "+f"(d[1]), "+f"(d[2]), "+f"(d[3])
        : "r"(a[0]), "r"(a[1]), "r"(a[2]), "r"(a[3]), "r"(b[0]), "r"(b[1]));
}

// ---------------------------------------------------------------------------
// GEMM stage loader (R13, unchanged)
// ---------------------------------------------------------------------------
__device__ __forceinline__ void load_stage_tk(uint32_t sb, int slot, int mt, int nt,
                                              int kt, int tid) {
    uint32_t abase = sb + slot * STAGE_BYTES;
    uint32_t bbase = abase + A_BYTES;
    size_t kbase = (size_t)kt * BKT;
#pragma unroll
    for (int q = 0; q < 4; q++) {
        int ci = q * NTHREADS + tid;
        int r = ci >> 3, c = ci & 7;
        uint32_t doff = r * 128 + ((c ^ (r & 7)) << 4);
        cp16(abase + doff, g_A + (size_t)(mt * BM + r) * KDIM + kbase + c * 8);
    }
#pragma unroll
    for (int q = 0; q < 2; q++) {
        int ci = q * NTHREADS + tid;
        int r = ci >> 3, c = ci & 7;
        uint32_t doff = r * 128 + ((c ^ (r & 7)) << 4);
        cp16(bbase + doff, g_B + (size_t)(nt * BN + r) * KDIM + kbase + c * 8);
    }
    asm volatile("cp.async.commit_group;" ::: "memory");
}

// ---------------------------------------------------------------------------
// Fused persistent kernel: prep -> global barrier -> GEMM
// ---------------------------------------------------------------------------
#define AROWS 4
__global__ __launch_bounds__(NTHREADS, 1)
void kan_fused(const float* __restrict__ x, const float* __restrict__ grid,
               const float* __restrict__ bw, const float* __restrict__ sw,
               const float* __restrict__ sc, float* __restrict__ out) {
    extern __shared__ char smem[];
    const uint32_t sb = smem_u32(smem);
    const int tid = threadIdx.x;

    // ======================= Phase 1: prep =======================
    {
        // staging: two 256-thread halves, each AROWS x (256*NPER) halves
        __half (*sh)[AROWS][256 * NPER] =
            reinterpret_cast<__half (*)[AROWS][256 * NPER]>(smem);
        const int half = tid >> 8;          // 0 / 1
        const int t = tid & 255;
        const int group = blockIdx.x * 2 + half;   // 0..295
        float4* out4 = (float4*)out;

#pragma unroll 1
        for (int w = 0; w < PREP_STEPS; w++) {
            const int blk = group + w * PREP_GROUPS;
            const bool active = blk < PREP_BLOCKS;

            // ---- fill phase ----
            if (active) {
                if (blk >= 8192) {
                    out4[(size_t)(blk - 8192) * 256 + t] = make_float4(0.f, 0.f, 0.f, 0.f);
                } else if (blk < 4096) {
                    // A: closed-form uniform cubic B-spline
                    const int i0 = (blk & 3) * 256;
                    const int i = i0 + t;
                    const int b0 = (blk >> 2) * AROWS;
                    const float g0 = grid[i * 12 + 0];
                    const float h  = grid[i * 12 + 1] - g0;
                    const float inv_h = __fdividef(1.0f, h);
                    const __half hz = __float2half_rn(0.0f);
#pragma unroll
                    for (int r = 0; r < AROWS; r++) {
                        float xv = x[(size_t)(b0 + r) * IN_F + i];
                        __half* fo = &sh[half][r][t * NPER];
                        fo[0] = __float2half_rn(xv * __fdividef(1.0f, 1.0f + __expf(-xv)));
#pragma unroll
                        for (int j = 1; j < NPER; j++) fo[j] = hz;
                        float tt = (xv - g0) * inv_h;
                        float fi = floorf(tt);
                        int idx = (int)fi;
                        if (idx >= 0 && idx <= 10) {
                            float u = tt - fi;
                            float u2 = u * u, u3 = u2 * u;
                            float om = 1.0f - u;
                            const float c6 = 1.0f / 6.0f;
                            float wgt[4];
                            wgt[0] = om * om * om * c6;
                            wgt[1] = (3.0f * u3 - 6.0f * u2 + 4.0f) * c6;
                            wgt[2] = (-3.0f * u3 + 3.0f * u2 + 3.0f * u + 1.0f) * c6;
                            wgt[3] = u3 * c6;
#pragma unroll
                            for (int q = 0; q < 4; q++) {
                                int j = idx - 3 + q;
                                if (j >= 0 && j < 8) fo[1 + j] = __float2half_rn(wgt[q]);
                            }
                        }
                    }
                } else {
                    // B: packed weights [bw | sw*sc]
                    const int q0 = blk - 4096;
                    const int i0 = (q0 & 3) * 256;
                    const int o = q0 >> 2;
                    const int oi = o * IN_F + i0 + t;
                    float scale = sc[oi];
                    __half* fo = &sh[half][0][t * NPER];
                    fo[0] = __float2half_rn(bw[oi]);
#pragma unroll
                    for (int j = 0; j < 8; j++)
                        fo[1 + j] = __float2half_rn(sw[(size_t)oi * 8 + j] * scale);
                }
            }
            __syncthreads();

            // ---- copy phase ----
            if (active && blk < 8192) {
                if (blk < 4096) {
                    const int i0 = (blk & 3) * 256;
                    const int b0 = (blk >> 2) * AROWS;
#pragma unroll
                    for (int r = 0; r < AROWS; r++) {
                        size_t base = (size_t)(b0 + r) * KDIM + (size_t)i0 * NPER;
                        const uint4* hs = (const uint4*)sh[half][r];
                        uint4* hd = (uint4*)(g_A + base);
                        for (int q = t; q < 256 * NPER * 2 / 16; q += 256) hd[q] = hs[q];
                    }
                } else {
                    const int q0 = blk - 4096;
                    const int i0 = (q0 & 3) * 256;
                    const int o = q0 >> 2;
                    size_t base = (size_t)o * KDIM + (size_t)i0 * NPER;
                    const uint4* hs = (const uint4*)sh[half][0];
                    uint4* hd = (uint4*)(g_B + base);
                    for (int q = t; q < 256 * NPER * 2 / 16; q += 256) hd[q] = hs[q];
                }
            }
            __syncthreads();
        }
    }

    // ================== global barrier (sense-reversing) ==================
    __threadfence();
    __syncthreads();
    if (tid == 0) {
        unsigned s = atomicAdd(&g_sense, 0u);
        if (atomicAdd(&g_count, 1u) == NWORKERS - 1) {
            g_count = 0;
            __threadfence();
            atomicExch(&g_sense, s ^ 1u);
        } else {
            while (atomicAdd(&g_sense, 0u) == s) {}
        }
    }
    __syncthreads();

    // ======================= Phase 2: GEMM (R13 body) =======================
    const int lane = tid & 31;
    const int wid = tid >> 5;
    const int warp_m = wid & 3;
    const int warp_n = wid >> 2;

    const int gs = (int)(((uint64_t)blockIdx.x * TOTAL_ITERS) / NWORKERS);
    const int ge = (int)(((uint64_t)(blockIdx.x + 1) * TOTAL_ITERS) / NWORKERS);

    float acc[4][4][4];
#pragma unroll
    for (int mf = 0; mf < 4; mf++)
#pragma unroll
        for (int nf = 0; nf < 4; nf++)
#pragma unroll
            for (int e = 0; e < 4; e++) acc[mf][nf][e] = 0.0f;

    const int a_row0 = warp_m * 64 + ((lane >> 3) & 1) * 8 + (lane & 7);
    const int a_chunk_hi = lane >> 4;
    const int bq = lane >> 3;
    const int b_row0 = warp_n * 32 + (bq >> 1) * 8 + (lane & 7);
    const int b_chunk_hi = bq & 1;

    uint32_t a_base[4], b_base[2];
    int a_x7[4], b_x7[2];
#pragma unroll
    for (int mf = 0; mf < 4; mf++) {
        int r = a_row0 + mf * 16;
        a_base[mf] = r * 128;
        a_x7[mf] = r & 7;
    }
#pragma unroll
    for (int p = 0; p < 2; p++) {
        int r = b_row0 + p * 16;
        b_base[p] = r * 128;
        b_x7[p] = r & 7;
    }

    int tile_c = gs / TILE_ITERS;
    int kt_c = gs - tile_c * TILE_ITERS;

    int tile_p = tile_c, kt_p = kt_c;
    load_stage_tk(sb, 0, tile_p >> 3, tile_p & 7, kt_p, tid);
    if (++kt_p == TILE_ITERS) { kt_p = 0; tile_p++; }
    if (gs + 1 < ge) load_stage_tk(sb, 1, tile_p >> 3, tile_p & 7, kt_p, tid);
    if (++kt_p == TILE_ITERS) { kt_p = 0; tile_p++; }
    if (gs + 2 < ge) load_stage_tk(sb, 2, tile_p >> 3, tile_p & 7, kt_p, tid);
    if (++kt_p == TILE_ITERS) { kt_p = 0; tile_p++; }

#pragma unroll 1
    for (int g = gs; g < ge; g++) {
        const int s = (g - gs) & (STAGES - 1);
        asm volatile("cp.async.wait_group %0;" :: "n"(STAGES - 2));
        __syncthreads();
        if (g + 3 < ge) {
            load_stage_tk(sb, (g - gs + 3) & (STAGES - 1), tile_p >> 3, tile_p & 7, kt_p, tid);
            if (++kt_p == TILE_ITERS) { kt_p = 0; tile_p++; }
        }

        const uint32_t abase = sb + s * STAGE_BYTES;
        const uint32_t bbase = abase + A_BYTES;

#pragma unroll
        for (int ks = 0; ks < 4; ks++) {
            uint32_t a[4][4], b[4][2];
#pragma unroll
            for (int mf = 0; mf < 4; mf++) {
                int c = ks * 2 + a_chunk_hi;
                ldsm_x4(a[mf], abase + a_base[mf] + ((c ^ a_x7[mf]) << 4));
            }
#pragma unroll
            for (int p = 0; p < 2; p++) {
                int c = ks * 2 + b_chunk_hi;
                uint32_t rr[4];
                ldsm_x4(rr, bbase + b_base[p] + ((c ^ b_x7[p]) << 4));
                b[p * 2 + 0][0] = rr[0]; b[p * 2 + 0][1] = rr[1];
                b[p * 2 + 1][0] = rr[2]; b[p * 2 + 1][1] = rr[3];
            }
#pragma unroll
            for (int mf = 0; mf < 4; mf++)
#pragma unroll
                for (int nf = 0; nf < 4; nf++)
                    mma_f16(acc[mf][nf], a[mf], b[nf]);
        }

        if (kt_c == TILE_ITERS - 1 || g == ge - 1) {
            const int mt = tile_c >> 3, nt = tile_c & 7;
            const int row_b = mt * BM + warp_m * 64 + (lane >> 2);
            const int col_b = nt * BN + warp_n * 32 + (lane & 3) * 2;
#pragma unroll
            for (int mf = 0; mf < 4; mf++)
#pragma unroll
                for (int nf = 0; nf < 4; nf++) {
                    float* p0 = out + (size_t)(row_b + mf * 16) * OUT_F + col_b + nf * 8;
                    float* p1 = p0 + 8 * OUT_F;
                    atomicAdd(p0,     acc[mf][nf][0]);
                    atomicAdd(p0 + 1, acc[mf][nf][1]);
                    atomicAdd(p1,     acc[mf][nf][2]);
                    atomicAdd(p1 + 1, acc[mf][nf][3]);
                    acc[mf][nf][0] = acc[mf][nf][1] = acc[mf][nf][2] = acc[mf][nf][3] = 0.0f;
                }
        }
        if (++kt_c == TILE_ITERS) { kt_c = 0; tile_c++; }
    }
}

// ---------------------------------------------------------------------------
extern "C" void kernel_launch(void* const* d_in, const int* in_sizes, int n_in,
                              void* d_out, int out_size) {
    const float* x    = (const float*)d_in[0];
    const float* bw   = (const float*)d_in[1];
    const float* sw   = (const float*)d_in[2];
    const float* sc   = (const float*)d_in[3];
    const float* grid = (const float*)d_in[4];
    float* out = (float*)d_out;
    (void)in_sizes; (void)n_in; (void)out_size;

    cudaFuncSetAttribute(kan_fused,
                         cudaFuncAttributeMaxDynamicSharedMemorySize, SMEM_BYTES);

    kan_fused<<<NWORKERS, NTHREADS, SMEM_BYTES>>>(x, grid, bw, sw, sc, out);
}

// round 17
// speedup vs baseline: 1.1239x; 1.1239x over previous
#include <cuda_runtime.h>
#include <cuda_fp16.h>
#include <stdint.h>
#include <math.h>

#define B_TOTAL 4096
#define IN_F    1024
#define OUT_F   1024
#define NPER    9
#define KDIM    (IN_F * NPER)        // 9216

#define BM 256
#define BN 128
#define BKT 64                        // k-extent per iteration
#define TILE_ITERS (KDIM / BKT)       // 144
#define MT_TILES (B_TOTAL / BM)       // 16
#define NT_TILES (OUT_F / BN)         // 8
#define TILES (MT_TILES * NT_TILES)   // 128
#define TOTAL_ITERS (TILES * TILE_ITERS)  // 18432
#define NWORKERS 148                  // 1 CTA per SM

#define NTHREADS 512
#define STAGES 4
#define A_BYTES (BM * BKT * 2)        // 32768
#define B_BYTES (BN * BKT * 2)        // 16384
#define STAGE_BYTES (A_BYTES + B_BYTES)      // 49152
#define SMEM_BYTES  (STAGES * STAGE_BYTES)   // 196608

// fp16 matrices, row-major [rows][KDIM]
__device__ __half g_A[(size_t)B_TOTAL * KDIM];
__device__ __half g_B[(size_t)OUT_F * KDIM];

// ---------------------------------------------------------------------------
// PTX helpers (sm_80/sm_90 baseline, legal on sm_100)
// ---------------------------------------------------------------------------
__device__ __forceinline__ uint32_t smem_u32(const void* p) {
    return (uint32_t)__cvta_generic_to_shared(p);
}
__device__ __forceinline__ void cp16(uint32_t dst, const void* src) {
    asm volatile("cp.async.cg.shared.global [%0], [%1], 16;" :: "r"(dst), "l"(src) : "memory");
}
__device__ __forceinline__ void ldsm_x4(uint32_t* r, uint32_t addr) {
    asm volatile("ldmatrix.sync.aligned.m8n8.x4.shared.b16 {%0,%1,%2,%3}, [%4];"
                 : "=r"(r[0]), "=r"(r[1]), "=r"(r[2]), "=r"(r[3]) : "r"(addr));
}
__device__ __forceinline__ void mma_f16(float* d, const uint32_t* a, const uint32_t* b) {
    asm volatile(
        "mma.sync.aligned.m16n8k16.row.col.f32.f16.f16.f32 "
        "{%0,%1,%2,%3}, {%4,%5,%6,%7}, {%8,%9}, {%0,%1,%2,%3};"
        : "+f"(d[0]), "+f"(d[1]), "+f"(d[2]), "+f"(d[3])
        : "r"(a[0]), "r"(a[1]), "r"(a[2]), "r"(a[3]), "r"(b[0]), "r"(b[1]));
}
__device__ __forceinline__ void red_add_v2(float* p, float v0, float v1) {
    asm volatile("red.global.add.v2.f32 [%0], {%1, %2};"
                 :: "l"(p), "f"(v0), "f"(v1) : "memory");
}

// ---------------------------------------------------------------------------
// Merged prep: blocks [0,4096) build A via closed-form uniform cubic
// B-spline; [4096,8192) build packed B; [8192,12288) zero-fill the output.
// ---------------------------------------------------------------------------
#define AROWS 4
__global__ __launch_bounds__(256)
void kan_prep(const float* __restrict__ x, const float* __restrict__ grid,
              const float* __restrict__ bw, const float* __restrict__ sw,
              const float* __restrict__ sc, float4* __restrict__ out) {
    __shared__ __half sh[AROWS][256 * NPER];
    const int tid = threadIdx.x;
    const int blk = blockIdx.x;

    if (blk >= 8192) {
        out[(size_t)(blk - 8192) * 256 + tid] = make_float4(0.f, 0.f, 0.f, 0.f);
        return;
    }

    if (blk < 4096) {
        // ---- A part: uniform-knot closed form ----
        const int i0 = (blk & 3) * 256;
        const int i = i0 + tid;
        const int b0 = (blk >> 2) * AROWS;

        const float g0 = grid[i * 12 + 0];
        const float h  = grid[i * 12 + 1] - g0;
        const float inv_h = __fdividef(1.0f, h);
        const __half hz = __float2half_rn(0.0f);

#pragma unroll
        for (int r = 0; r < AROWS; r++) {
            float xv = x[(size_t)(b0 + r) * IN_F + i];
            __half* fo = &sh[r][tid * NPER];

            fo[0] = __float2half_rn(xv * __fdividef(1.0f, 1.0f + __expf(-xv)));
#pragma unroll
            for (int j = 1; j < NPER; j++) fo[j] = hz;

            float t = (xv - g0) * inv_h;
            float fi = floorf(t);
            int idx = (int)fi;
            if (idx >= 0 && idx <= 10) {
                float u = t - fi;
                float u2 = u * u, u3 = u2 * u;
                float om = 1.0f - u;
                const float c6 = 1.0f / 6.0f;
                float w[4];
                w[0] = om * om * om * c6;
                w[1] = (3.0f * u3 - 6.0f * u2 + 4.0f) * c6;
                w[2] = (-3.0f * u3 + 3.0f * u2 + 3.0f * u + 1.0f) * c6;
                w[3] = u3 * c6;
#pragma unroll
                for (int q = 0; q < 4; q++) {
                    int j = idx - 3 + q;
                    if (j >= 0 && j < 8) fo[1 + j] = __float2half_rn(w[q]);
                }
            }
        }
        __syncthreads();

#pragma unroll
        for (int r = 0; r < AROWS; r++) {
            size_t base = (size_t)(b0 + r) * KDIM + (size_t)i0 * NPER;
            const uint4* hs = (const uint4*)sh[r];
            uint4* hd = (uint4*)(g_A + base);
            for (int q = tid; q < 256 * NPER * 2 / 16; q += 256) hd[q] = hs[q];
        }
    } else {
        // ---- B part: packed weights [bw | sw*sc], vectorized sw reads ----
        const int q0 = blk - 4096;
        const int i0 = (q0 & 3) * 256;
        const int o = q0 >> 2;
        const int oi = o * IN_F + i0 + tid;

        float scale = sc[oi];
        const float4* sw4 = (const float4*)(sw + (size_t)oi * 8);
        float4 s0 = sw4[0], s1 = sw4[1];
        __half* fo = &sh[0][tid * NPER];
        fo[0] = __float2half_rn(bw[oi]);
        fo[1] = __float2half_rn(s0.x * scale);
        fo[2] = __float2half_rn(s0.y * scale);
        fo[3] = __float2half_rn(s0.z * scale);
        fo[4] = __float2half_rn(s0.w * scale);
        fo[5] = __float2half_rn(s1.x * scale);
        fo[6] = __float2half_rn(s1.y * scale);
        fo[7] = __float2half_rn(s1.z * scale);
        fo[8] = __float2half_rn(s1.w * scale);
        __syncthreads();

        size_t base = (size_t)o * KDIM + (size_t)i0 * NPER;
        const uint4* hs = (const uint4*)sh[0];
        uint4* hd = (uint4*)(g_B + base);
        for (int q = tid; q < 256 * NPER * 2 / 16; q += 256) hd[q] = hs[q];
    }
}

// ---------------------------------------------------------------------------
// Persistent fp16 GEMM, 256x128 tile, 512 threads (16 warps as 4x4),
// 4-stage cp.async pipeline; 148 equal contiguous spans; incremental
// (tile, kt) cursors; boundary tiles merged via red.global.add.v2.
// ---------------------------------------------------------------------------
__device__ __forceinline__ void load_stage_tk(uint32_t sb, int slot, int mt, int nt,
                                              int kt, int tid) {
    uint32_t abase = sb + slot * STAGE_BYTES;
    uint32_t bbase = abase + A_BYTES;
    size_t kbase = (size_t)kt * BKT;
#pragma unroll
    for (int q = 0; q < 4; q++) {
        int ci = q * NTHREADS + tid;
        int r = ci >> 3, c = ci & 7;
        uint32_t doff = r * 128 + ((c ^ (r & 7)) << 4);
        cp16(abase + doff, g_A + (size_t)(mt * BM + r) * KDIM + kbase + c * 8);
    }
#pragma unroll
    for (int q = 0; q < 2; q++) {
        int ci = q * NTHREADS + tid;
        int r = ci >> 3, c = ci & 7;
        uint32_t doff = r * 128 + ((c ^ (r & 7)) << 4);
        cp16(bbase + doff, g_B + (size_t)(nt * BN + r) * KDIM + kbase + c * 8);
    }
    asm volatile("cp.async.commit_group;" ::: "memory");
}

__global__ __launch_bounds__(NTHREADS, 1)
void kan_mma_kernel(float* __restrict__ out) {
    extern __shared__ char smem[];
    const uint32_t sb = smem_u32(smem);
    const int tid = threadIdx.x;
    const int lane = tid & 31;
    const int wid = tid >> 5;
    const int warp_m = wid & 3;       // 4 x 64 rows = 256
    const int warp_n = wid >> 2;      // 4 x 32 cols = 128

    const int gs = (int)(((uint64_t)blockIdx.x * TOTAL_ITERS) / NWORKERS);
    const int ge = (int)(((uint64_t)(blockIdx.x + 1) * TOTAL_ITERS) / NWORKERS);

    float acc[4][4][4];
#pragma unroll
    for (int mf = 0; mf < 4; mf++)
#pragma unroll
        for (int nf = 0; nf < 4; nf++)
#pragma unroll
            for (int e = 0; e < 4; e++) acc[mf][nf][e] = 0.0f;

    const int a_row0 = warp_m * 64 + ((lane >> 3) & 1) * 8 + (lane & 7);
    const int a_chunk_hi = lane >> 4;
    const int bq = lane >> 3;
    const int b_row0 = warp_n * 32 + (bq >> 1) * 8 + (lane & 7);
    const int b_chunk_hi = bq & 1;

    uint32_t a_base[4], b_base[2];
    int a_x7[4], b_x7[2];
#pragma unroll
    for (int mf = 0; mf < 4; mf++) {
        int r = a_row0 + mf * 16;
        a_base[mf] = r * 128;
        a_x7[mf] = r & 7;
    }
#pragma unroll
    for (int p = 0; p < 2; p++) {
        int r = b_row0 + p * 16;
        b_base[p] = r * 128;
        b_x7[p] = r & 7;
    }

    int tile_c = gs / TILE_ITERS;
    int kt_c = gs - tile_c * TILE_ITERS;

    int tile_p = tile_c, kt_p = kt_c;
    load_stage_tk(sb, 0, tile_p >> 3, tile_p & 7, kt_p, tid);
    if (++kt_p == TILE_ITERS) { kt_p = 0; tile_p++; }
    if (gs + 1 < ge) load_stage_tk(sb, 1, tile_p >> 3, tile_p & 7, kt_p, tid);
    if (++kt_p == TILE_ITERS) { kt_p = 0; tile_p++; }
    if (gs + 2 < ge) load_stage_tk(sb, 2, tile_p >> 3, tile_p & 7, kt_p, tid);
    if (++kt_p == TILE_ITERS) { kt_p = 0; tile_p++; }

#pragma unroll 1
    for (int g = gs; g < ge; g++) {
        const int s = (g - gs) & (STAGES - 1);
        asm volatile("cp.async.wait_group %0;" :: "n"(STAGES - 2));
        __syncthreads();
        if (g + 3 < ge) {
            load_stage_tk(sb, (g - gs + 3) & (STAGES - 1), tile_p >> 3, tile_p & 7, kt_p, tid);
            if (++kt_p == TILE_ITERS) { kt_p = 0; tile_p++; }
        }

        const uint32_t abase = sb + s * STAGE_BYTES;
        const uint32_t bbase = abase + A_BYTES;

#pragma unroll
        for (int ks = 0; ks < 4; ks++) {
            uint32_t a[4][4], b[4][2];
#pragma unroll
            for (int mf = 0; mf < 4; mf++) {
                int c = ks * 2 + a_chunk_hi;
                ldsm_x4(a[mf], abase + a_base[mf] + ((c ^ a_x7[mf]) << 4));
            }
#pragma unroll
            for (int p = 0; p < 2; p++) {
                int c = ks * 2 + b_chunk_hi;
                uint32_t rr[4];
                ldsm_x4(rr, bbase + b_base[p] + ((c ^ b_x7[p]) << 4));
                b[p * 2 + 0][0] = rr[0]; b[p * 2 + 0][1] = rr[1];
                b[p * 2 + 1][0] = rr[2]; b[p * 2 + 1][1] = rr[3];
            }
#pragma unroll
            for (int mf = 0; mf < 4; mf++)
#pragma unroll
                for (int nf = 0; nf < 4; nf++)
                    mma_f16(acc[mf][nf], a[mf], b[nf]);
        }

        // flush at tile boundary or task end (vector reductions)
        if (kt_c == TILE_ITERS - 1 || g == ge - 1) {
            const int mt = tile_c >> 3, nt = tile_c & 7;
            const int row_b = mt * BM + warp_m * 64 + (lane >> 2);
            const int col_b = nt * BN + warp_n * 32 + (lane & 3) * 2;
#pragma unroll
            for (int mf = 0; mf < 4; mf++)
#pragma unroll
                for (int nf = 0; nf < 4; nf++) {
                    float* p0 = out + (size_t)(row_b + mf * 16) * OUT_F + col_b + nf * 8;
                    float* p1 = p0 + 8 * OUT_F;
                    red_add_v2(p0, acc[mf][nf][0], acc[mf][nf][1]);
                    red_add_v2(p1, acc[mf][nf][2], acc[mf][nf][3]);
                    acc[mf][nf][0] = acc[mf][nf][1] = acc[mf][nf][2] = acc[mf][nf][3] = 0.0f;
                }
        }
        if (++kt_c == TILE_ITERS) { kt_c = 0; tile_c++; }
    }
}

// ---------------------------------------------------------------------------
extern "C" void kernel_launch(void* const* d_in, const int* in_sizes, int n_in,
                              void* d_out, int out_size) {
    const float* x    = (const float*)d_in[0];
    const float* bw   = (const float*)d_in[1];
    const float* sw   = (const float*)d_in[2];
    const float* sc   = (const float*)d_in[3];
    const float* grid = (const float*)d_in[4];
    float* out = (float*)d_out;
    (void)in_sizes; (void)n_in; (void)out_size;

    cudaFuncSetAttribute(kan_mma_kernel,
                         cudaFuncAttributeMaxDynamicSharedMemorySize, SMEM_BYTES);

    kan_prep<<<12288, 256>>>(x, grid, bw, sw, sc, (float4*)out);
    kan_mma_kernel<<<NWORKERS, NTHREADS, SMEM_BYTES>>>(out);
}